// round 3
// baseline (speedup 1.0000x reference)
#include <cuda_runtime.h>
#include <math.h>

#define N_NODES   100000
#define C_DIM     64          // 64 floats = 32 float2 per row, 256B
#define C2        32          // float2 per row
#define E_EDGES   3200000
#define NUM_LAYERS 10
#define ALPHA     0.9f
#define ONE_M_ALPHA 0.1f

// ---- static device scratch (no allocation allowed) ----
__device__ int   g_deg[N_NODES];
__device__ int   g_rowptr[N_NODES + 1];
__device__ int   g_cursor[N_NODES];
__device__ int   g_col[E_EDGES];
__device__ float g_norm[N_NODES];
__device__ float g_last[N_NODES * C_DIM];
__device__ float g_zA[N_NODES * C_DIM];
__device__ float g_zB[N_NODES * C_DIM];
__device__ int   g_mask_is_byte;

// ------------------------------------------------------------------
// 0) detect mask element width: if any byte at offset %4 != 0 within the
//    first 1KB is nonzero, the mask is a 1-byte bool array; otherwise int32.
//    (all-zero prefix => int32 path; for an actually-all-false bool mask the
//    two interpretations give the same values, so it is still correct.)
__global__ void detect_mask_kernel(const unsigned char* __restrict__ m) {
    __shared__ int any;
    int t = threadIdx.x;
    if (t == 0) any = 0;
    __syncthreads();
    for (int i = t; i < 1024; i += blockDim.x) {
        if ((i & 3) != 0 && m[i] != 0) atomicOr(&any, 1);
    }
    __syncthreads();
    if (t == 0) g_mask_is_byte = any;
}

// 1) zero degree counters
__global__ void zero_deg_kernel(int n) {
    int i = blockIdx.x * blockDim.x + threadIdx.x;
    if (i < n) g_deg[i] = 0;
}

// 2) count in-degrees (segment count at dst)
__global__ void count_deg_kernel(const int* __restrict__ dst, int e) {
    int i = blockIdx.x * blockDim.x + threadIdx.x;
    if (i < e) {
        int d = dst[i];
        if (d >= 0 && d < N_NODES) atomicAdd(&g_deg[d], 1);
    }
}

// 3) single-block exclusive scan -> rowptr, cursor; also norm = rsqrt(max(deg,1))
__global__ void scan_kernel(int n) {
    __shared__ int sh[1024];
    __shared__ int carry;
    int t = threadIdx.x;
    if (t == 0) carry = 0;
    __syncthreads();
    for (int base = 0; base < n; base += 1024) {
        int i = base + t;
        int v = (i < n) ? g_deg[i] : 0;
        sh[t] = v;
        __syncthreads();
        // Kogge-Stone inclusive scan
        #pragma unroll
        for (int off = 1; off < 1024; off <<= 1) {
            int add = (t >= off) ? sh[t - off] : 0;
            __syncthreads();
            sh[t] += add;
            __syncthreads();
        }
        int incl = sh[t];
        if (i < n) {
            int excl = carry + incl - v;
            g_rowptr[i] = excl;
            g_cursor[i] = excl;
            g_norm[i]   = rsqrtf((float)(v > 0 ? v : 1));
        }
        __syncthreads();                 // everyone has read carry
        if (t == 1023) carry += sh[1023];
        __syncthreads();
    }
    if (t == 0) g_rowptr[n] = carry;
}

// 4) scatter edges into CSR (by dst)
__global__ void fill_csr_kernel(const int* __restrict__ src,
                                const int* __restrict__ dst, int e) {
    int i = blockIdx.x * blockDim.x + threadIdx.x;
    if (i < e) {
        int d = dst[i];
        int s = src[i];
        if (d >= 0 && d < N_NODES && s >= 0 && s < N_NODES) {
            int p = atomicAdd(&g_cursor[d], 1);
            g_col[p] = s;
        }
    }
}

// 5) init: y0 = mask ? labels : 0; last = 0.1*y0; zA = norm*y0
__global__ void init_kernel(const float* __restrict__ labels,
                            const void* __restrict__ mask_raw, int n) {
    int idx = blockIdx.x * blockDim.x + threadIdx.x;   // over n*C2 float2s
    if (idx >= n * C2) return;
    int node = idx >> 5;
    float2 l = ((const float2*)labels)[idx];
    int mv;
    if (g_mask_is_byte) {
        mv = ((const unsigned char*)mask_raw)[node];
    } else {
        mv = ((const int*)mask_raw)[node];
    }
    float m  = mv ? 1.0f : 0.0f;
    float vx = l.x * m, vy = l.y * m;
    ((float2*)g_last)[idx] = make_float2(ONE_M_ALPHA * vx, ONE_M_ALPHA * vy);
    float nn = g_norm[node];
    ((float2*)g_zA)[idx] = make_float2(nn * vx, nn * vy);
}

// 6) one propagation layer: warp per dst node, float2 per lane.
//    zin -> (gather/sum) -> y = clip(last + alpha*norm*acc); zout = norm*y
//    (final layer: write y to yout instead of z)
__global__ void __launch_bounds__(256)
prop_kernel(int flip, float* __restrict__ yout) {
    const float2* __restrict__ zin = (const float2*)(flip ? g_zB : g_zA);
    float2* __restrict__ zout      = (float2*)(flip ? g_zA : g_zB);

    int gwarp = (blockIdx.x * blockDim.x + threadIdx.x) >> 5;
    int lane  = threadIdx.x & 31;
    if (gwarp >= N_NODES) return;

    int beg = g_rowptr[gwarp];
    int end = g_rowptr[gwarp + 1];

    float ax = 0.0f, ay = 0.0f;
    int j = beg;
    for (; j + 4 <= end; j += 4) {
        int s0 = g_col[j + 0];
        int s1 = g_col[j + 1];
        int s2 = g_col[j + 2];
        int s3 = g_col[j + 3];
        float2 v0 = zin[s0 * C2 + lane];
        float2 v1 = zin[s1 * C2 + lane];
        float2 v2 = zin[s2 * C2 + lane];
        float2 v3 = zin[s3 * C2 + lane];
        ax += (v0.x + v1.x) + (v2.x + v3.x);
        ay += (v0.y + v1.y) + (v2.y + v3.y);
    }
    for (; j < end; j++) {
        int s = g_col[j];
        float2 v = zin[s * C2 + lane];
        ax += v.x;
        ay += v.y;
    }

    float nd = g_norm[gwarp];
    float2 l = ((const float2*)g_last)[gwarp * C2 + lane];
    float yx = fminf(fmaxf(fmaf(ALPHA * nd, ax, l.x), 0.0f), 1.0f);
    float yy = fminf(fmaxf(fmaf(ALPHA * nd, ay, l.y), 0.0f), 1.0f);

    if (yout) {
        ((float2*)yout)[gwarp * C2 + lane] = make_float2(yx, yy);
    } else {
        zout[gwarp * C2 + lane] = make_float2(nd * yx, nd * yy);
    }
}

// ------------------------------------------------------------------
extern "C" void kernel_launch(void* const* d_in, const int* in_sizes, int n_in,
                              void* d_out, int out_size) {
    const float* labels   = (const float*)d_in[0];
    const void*  mask_raw = d_in[1];
    const int*   src      = (const int*)d_in[2];
    const int*   dst      = (const int*)d_in[3];
    float*       out      = (float*)d_out;

    const int N = N_NODES;
    const int E = E_EDGES;

    // mask dtype detection (device-side, deterministic, capturable)
    detect_mask_kernel<<<1, 256>>>((const unsigned char*)mask_raw);

    // CSR build
    zero_deg_kernel<<<(N + 255) / 256, 256>>>(N);
    count_deg_kernel<<<(E + 255) / 256, 256>>>(dst, E);
    scan_kernel<<<1, 1024>>>(N);
    fill_csr_kernel<<<(E + 255) / 256, 256>>>(src, dst, E);

    // init y0 / last / z0
    init_kernel<<<(N * C2 + 255) / 256, 256>>>(labels, mask_raw, N);

    // 10 propagation layers, ping-pong z buffers, final layer writes d_out
    const int warps_per_block = 256 / 32;
    const int prop_blocks = (N + warps_per_block - 1) / warps_per_block;
    for (int layer = 0; layer < NUM_LAYERS; layer++) {
        int flip = layer & 1;                 // 0: zA->zB, 1: zB->zA
        float* yo = (layer == NUM_LAYERS - 1) ? out : nullptr;
        prop_kernel<<<prop_blocks, 256>>>(flip, yo);
    }
}

// round 4
// speedup vs baseline: 1.3439x; 1.3439x over previous
#include <cuda_runtime.h>
#include <cuda_fp16.h>
#include <math.h>

#define N_NODES   100000
#define C_DIM     64
#define C2        32          // pairs per row
#define E_EDGES   3200000
#define NUM_LAYERS 10
#define ALPHA     0.9f
#define ONE_M_ALPHA 0.1f
#define SCAN_TILE 1024
#define NBLK_SCAN ((N_NODES + SCAN_TILE - 1) / SCAN_TILE)   // 98

// ---- static device scratch (no allocation allowed) ----
__device__ int     g_deg[N_NODES];
__device__ int     g_rowptr[N_NODES + 1];
__device__ int     g_cursor[N_NODES];
__device__ int     g_col[E_EDGES];
__device__ int     g_part[NBLK_SCAN];
__device__ float   g_norm[N_NODES];
__device__ float   g_last[N_NODES * C_DIM];
__device__ __half2 g_zA[N_NODES * C2];
__device__ __half2 g_zB[N_NODES * C2];
__device__ int     g_mask_is_byte;

// ------------------------------------------------------------------
// 0) detect mask element width (byte-bool vs int32)
__global__ void detect_mask_kernel(const unsigned char* __restrict__ m) {
    __shared__ int any;
    int t = threadIdx.x;
    if (t == 0) any = 0;
    __syncthreads();
    for (int i = t; i < 1024; i += blockDim.x) {
        if ((i & 3) != 0 && m[i] != 0) atomicOr(&any, 1);
    }
    __syncthreads();
    if (t == 0) g_mask_is_byte = any;
}

// 1) zero degree counters
__global__ void zero_deg_kernel(int n) {
    int i = blockIdx.x * blockDim.x + threadIdx.x;
    if (i < n) g_deg[i] = 0;
}

// 2) count in-degrees
__global__ void count_deg_kernel(const int* __restrict__ dst, int e) {
    int i = blockIdx.x * blockDim.x + threadIdx.x;
    if (i < e) {
        int d = dst[i];
        if (d >= 0 && d < N_NODES) atomicAdd(&g_deg[d], 1);
    }
}

// 3a) per-block sums of degrees
__global__ void __launch_bounds__(SCAN_TILE)
scan_pass1_kernel(int n) {
    __shared__ int sh[SCAN_TILE];
    int i = blockIdx.x * SCAN_TILE + threadIdx.x;
    sh[threadIdx.x] = (i < n) ? g_deg[i] : 0;
    __syncthreads();
    #pragma unroll
    for (int off = SCAN_TILE / 2; off > 0; off >>= 1) {
        if (threadIdx.x < off) sh[threadIdx.x] += sh[threadIdx.x + off];
        __syncthreads();
    }
    if (threadIdx.x == 0) g_part[blockIdx.x] = sh[0];
}

// 3b) exclusive scan of the (tiny) partials array; also total -> rowptr[n]
__global__ void scan_pass2_kernel(int n) {
    __shared__ int sh[128];
    int t = threadIdx.x;
    int v = (t < NBLK_SCAN) ? g_part[t] : 0;
    sh[t] = v;
    __syncthreads();
    #pragma unroll
    for (int off = 1; off < 128; off <<= 1) {
        int add = (t >= off) ? sh[t - off] : 0;
        __syncthreads();
        sh[t] += add;
        __syncthreads();
    }
    if (t < NBLK_SCAN) g_part[t] = sh[t] - v;      // exclusive
    if (t == 127) g_rowptr[n] = sh[127];           // total
}

// 3c) block-local exclusive scan + block offset -> rowptr/cursor/norm
__global__ void __launch_bounds__(SCAN_TILE)
scan_pass3_kernel(int n) {
    __shared__ int sh[SCAN_TILE];
    int t = threadIdx.x;
    int i = blockIdx.x * SCAN_TILE + t;
    int v = (i < n) ? g_deg[i] : 0;
    sh[t] = v;
    __syncthreads();
    #pragma unroll
    for (int off = 1; off < SCAN_TILE; off <<= 1) {
        int add = (t >= off) ? sh[t - off] : 0;
        __syncthreads();
        sh[t] += add;
        __syncthreads();
    }
    if (i < n) {
        int excl = g_part[blockIdx.x] + sh[t] - v;
        g_rowptr[i] = excl;
        g_cursor[i] = excl;
        g_norm[i]   = rsqrtf((float)(v > 0 ? v : 1));
    }
}

// 4) scatter edges into CSR (by dst)
__global__ void fill_csr_kernel(const int* __restrict__ src,
                                const int* __restrict__ dst, int e) {
    int i = blockIdx.x * blockDim.x + threadIdx.x;
    if (i < e) {
        int d = dst[i];
        int s = src[i];
        if (d >= 0 && d < N_NODES && s >= 0 && s < N_NODES) {
            int p = atomicAdd(&g_cursor[d], 1);
            g_col[p] = s;
        }
    }
}

// 5) init: y0 = mask ? labels : 0; last = 0.1*y0; zA = half(norm*y0)
__global__ void init_kernel(const float* __restrict__ labels,
                            const void* __restrict__ mask_raw, int n) {
    int idx = blockIdx.x * blockDim.x + threadIdx.x;   // over n*C2 pairs
    if (idx >= n * C2) return;
    int node = idx >> 5;
    float2 l = ((const float2*)labels)[idx];
    int mv = g_mask_is_byte ? (int)((const unsigned char*)mask_raw)[node]
                            : ((const int*)mask_raw)[node];
    float m  = mv ? 1.0f : 0.0f;
    float vx = l.x * m, vy = l.y * m;
    ((float2*)g_last)[idx] = make_float2(ONE_M_ALPHA * vx, ONE_M_ALPHA * vy);
    float nn = g_norm[node];
    g_zA[idx] = __floats2half2_rn(nn * vx, nn * vy);
}

// 6) one propagation layer: warp per dst node, half2 per lane, fp32 accum.
__global__ void __launch_bounds__(256)
prop_kernel(int flip, float* __restrict__ yout) {
    const __half2* __restrict__ zin = flip ? g_zB : g_zA;
    __half2* __restrict__ zout      = flip ? g_zA : g_zB;

    int gwarp = (blockIdx.x * blockDim.x + threadIdx.x) >> 5;
    int lane  = threadIdx.x & 31;
    if (gwarp >= N_NODES) return;

    int beg = g_rowptr[gwarp];
    int end = g_rowptr[gwarp + 1];

    float ax = 0.0f, ay = 0.0f;
    int j = beg;
    for (; j + 4 <= end; j += 4) {
        int s0 = g_col[j + 0];
        int s1 = g_col[j + 1];
        int s2 = g_col[j + 2];
        int s3 = g_col[j + 3];
        float2 v0 = __half22float2(zin[s0 * C2 + lane]);
        float2 v1 = __half22float2(zin[s1 * C2 + lane]);
        float2 v2 = __half22float2(zin[s2 * C2 + lane]);
        float2 v3 = __half22float2(zin[s3 * C2 + lane]);
        ax += (v0.x + v1.x) + (v2.x + v3.x);
        ay += (v0.y + v1.y) + (v2.y + v3.y);
    }
    for (; j < end; j++) {
        float2 v = __half22float2(zin[g_col[j] * C2 + lane]);
        ax += v.x;
        ay += v.y;
    }

    float nd = g_norm[gwarp];
    float2 l = ((const float2*)g_last)[gwarp * C2 + lane];
    float yx = fminf(fmaxf(fmaf(ALPHA * nd, ax, l.x), 0.0f), 1.0f);
    float yy = fminf(fmaxf(fmaf(ALPHA * nd, ay, l.y), 0.0f), 1.0f);

    if (yout) {
        ((float2*)yout)[gwarp * C2 + lane] = make_float2(yx, yy);
    } else {
        zout[gwarp * C2 + lane] = __floats2half2_rn(nd * yx, nd * yy);
    }
}

// ------------------------------------------------------------------
extern "C" void kernel_launch(void* const* d_in, const int* in_sizes, int n_in,
                              void* d_out, int out_size) {
    const float* labels   = (const float*)d_in[0];
    const void*  mask_raw = d_in[1];
    const int*   src      = (const int*)d_in[2];
    const int*   dst      = (const int*)d_in[3];
    float*       out      = (float*)d_out;

    const int N = N_NODES;
    const int E = E_EDGES;

    detect_mask_kernel<<<1, 256>>>((const unsigned char*)mask_raw);

    // CSR build
    zero_deg_kernel<<<(N + 255) / 256, 256>>>(N);
    count_deg_kernel<<<(E + 255) / 256, 256>>>(dst, E);
    scan_pass1_kernel<<<NBLK_SCAN, SCAN_TILE>>>(N);
    scan_pass2_kernel<<<1, 128>>>(N);
    scan_pass3_kernel<<<NBLK_SCAN, SCAN_TILE>>>(N);
    fill_csr_kernel<<<(E + 255) / 256, 256>>>(src, dst, E);

    // init
    init_kernel<<<(N * C2 + 255) / 256, 256>>>(labels, mask_raw, N);

    // 10 propagation layers
    const int warps_per_block = 256 / 32;
    const int prop_blocks = (N + warps_per_block - 1) / warps_per_block;
    for (int layer = 0; layer < NUM_LAYERS; layer++) {
        int flip = layer & 1;
        float* yo = (layer == NUM_LAYERS - 1) ? out : nullptr;
        prop_kernel<<<prop_blocks, 256>>>(flip, yo);
    }
}

// round 5
// speedup vs baseline: 1.9220x; 1.4302x over previous
#include <cuda_runtime.h>
#include <cuda_fp16.h>
#include <math.h>

#define N_NODES   100000
#define C_DIM     64
#define C2        32          // half2 pairs per row
#define E_EDGES   3200000
#define NUM_LAYERS 10
#define ALPHA     0.9f
#define ONE_M_ALPHA 0.1f
#define SCAN_TILE 1024
#define NBLK_SCAN ((N_NODES + SCAN_TILE - 1) / SCAN_TILE)   // 98

// ---- static device scratch (no allocation allowed) ----
__device__ int     g_deg[N_NODES];
__device__ int     g_rowptr[N_NODES + 1];
__device__ int     g_cursor[N_NODES];
__device__ int     g_col[E_EDGES];
__device__ int     g_part[NBLK_SCAN];
__device__ float   g_norm[N_NODES];
__device__ float   g_last[N_NODES * C_DIM];
__device__ __half2 g_zA[N_NODES * C2];
__device__ __half2 g_zB[N_NODES * C2];
__device__ int     g_mask_is_byte;

// ------------------------------------------------------------------
__global__ void detect_mask_kernel(const unsigned char* __restrict__ m) {
    __shared__ int any;
    int t = threadIdx.x;
    if (t == 0) any = 0;
    __syncthreads();
    for (int i = t; i < 1024; i += blockDim.x) {
        if ((i & 3) != 0 && m[i] != 0) atomicOr(&any, 1);
    }
    __syncthreads();
    if (t == 0) g_mask_is_byte = any;
}

__global__ void zero_deg_kernel(int n) {
    int i = blockIdx.x * blockDim.x + threadIdx.x;
    if (i < n) g_deg[i] = 0;
}

__global__ void count_deg_kernel(const int* __restrict__ dst, int e) {
    int i = blockIdx.x * blockDim.x + threadIdx.x;
    if (i < e) {
        int d = dst[i];
        if (d >= 0 && d < N_NODES) atomicAdd(&g_deg[d], 1);
    }
}

__global__ void __launch_bounds__(SCAN_TILE)
scan_pass1_kernel(int n) {
    __shared__ int sh[SCAN_TILE];
    int i = blockIdx.x * SCAN_TILE + threadIdx.x;
    sh[threadIdx.x] = (i < n) ? g_deg[i] : 0;
    __syncthreads();
    #pragma unroll
    for (int off = SCAN_TILE / 2; off > 0; off >>= 1) {
        if (threadIdx.x < off) sh[threadIdx.x] += sh[threadIdx.x + off];
        __syncthreads();
    }
    if (threadIdx.x == 0) g_part[blockIdx.x] = sh[0];
}

__global__ void scan_pass2_kernel(int n) {
    __shared__ int sh[128];
    int t = threadIdx.x;
    int v = (t < NBLK_SCAN) ? g_part[t] : 0;
    sh[t] = v;
    __syncthreads();
    #pragma unroll
    for (int off = 1; off < 128; off <<= 1) {
        int add = (t >= off) ? sh[t - off] : 0;
        __syncthreads();
        sh[t] += add;
        __syncthreads();
    }
    if (t < NBLK_SCAN) g_part[t] = sh[t] - v;      // exclusive
    if (t == 127) g_rowptr[n] = sh[127];           // total
}

__global__ void __launch_bounds__(SCAN_TILE)
scan_pass3_kernel(int n) {
    __shared__ int sh[SCAN_TILE];
    int t = threadIdx.x;
    int i = blockIdx.x * SCAN_TILE + t;
    int v = (i < n) ? g_deg[i] : 0;
    sh[t] = v;
    __syncthreads();
    #pragma unroll
    for (int off = 1; off < SCAN_TILE; off <<= 1) {
        int add = (t >= off) ? sh[t - off] : 0;
        __syncthreads();
        sh[t] += add;
        __syncthreads();
    }
    if (i < n) {
        int excl = g_part[blockIdx.x] + sh[t] - v;
        g_rowptr[i] = excl;
        g_cursor[i] = excl;
        g_norm[i]   = rsqrtf((float)(v > 0 ? v : 1));
    }
}

__global__ void fill_csr_kernel(const int* __restrict__ src,
                                const int* __restrict__ dst, int e) {
    int i = blockIdx.x * blockDim.x + threadIdx.x;
    if (i < e) {
        int d = dst[i];
        int s = src[i];
        if (d >= 0 && d < N_NODES && s >= 0 && s < N_NODES) {
            int p = atomicAdd(&g_cursor[d], 1);
            g_col[p] = s;
        }
    }
}

__global__ void init_kernel(const float* __restrict__ labels,
                            const void* __restrict__ mask_raw, int n) {
    int idx = blockIdx.x * blockDim.x + threadIdx.x;   // over n*C2 pairs
    if (idx >= n * C2) return;
    int node = idx >> 5;
    float2 l = ((const float2*)labels)[idx];
    int mv = g_mask_is_byte ? (int)((const unsigned char*)mask_raw)[node]
                            : ((const int*)mask_raw)[node];
    float m  = mv ? 1.0f : 0.0f;
    float vx = l.x * m, vy = l.y * m;
    ((float2*)g_last)[idx] = make_float2(ONE_M_ALPHA * vx, ONE_M_ALPHA * vy);
    float nn = g_norm[node];
    g_zA[idx] = __floats2half2_rn(nn * vx, nn * vy);
}

// ------------------------------------------------------------------
// propagation layer: 8 lanes per dst node ("subwarp"), each lane owns a
// 16B chunk (8 halves) of the 128B row. 4 nodes per warp. fp32 accumulate.
__device__ __forceinline__ void acc_chunk(float2* a, uint4 v) {
    float2 t;
    t = __half22float2(*(const __half2*)&v.x); a[0].x += t.x; a[0].y += t.y;
    t = __half22float2(*(const __half2*)&v.y); a[1].x += t.x; a[1].y += t.y;
    t = __half22float2(*(const __half2*)&v.z); a[2].x += t.x; a[2].y += t.y;
    t = __half22float2(*(const __half2*)&v.w); a[3].x += t.x; a[3].y += t.y;
}

__global__ void __launch_bounds__(256)
prop_kernel(int flip, float* __restrict__ yout) {
    const uint4* __restrict__ zin = (const uint4*)(flip ? g_zB : g_zA);
    uint4* __restrict__ zout      = (uint4*)(flip ? g_zA : g_zB);

    int tid   = blockIdx.x * blockDim.x + threadIdx.x;
    int node  = tid >> 3;         // 8 lanes per node
    int slane = tid & 7;
    if (node >= N_NODES) return;

    int beg = g_rowptr[node];
    int end = g_rowptr[node + 1];

    float2 a[4];
    a[0] = a[1] = a[2] = a[3] = make_float2(0.0f, 0.0f);

    int j = beg;
    for (; j + 4 <= end; j += 4) {
        int s0 = g_col[j + 0];
        int s1 = g_col[j + 1];
        int s2 = g_col[j + 2];
        int s3 = g_col[j + 3];
        uint4 v0 = zin[s0 * 8 + slane];
        uint4 v1 = zin[s1 * 8 + slane];
        uint4 v2 = zin[s2 * 8 + slane];
        uint4 v3 = zin[s3 * 8 + slane];
        acc_chunk(a, v0);
        acc_chunk(a, v1);
        acc_chunk(a, v2);
        acc_chunk(a, v3);
    }
    for (; j < end; j++) {
        uint4 v = zin[g_col[j] * 8 + slane];
        acc_chunk(a, v);
    }

    float nd = g_norm[node];
    float s  = ALPHA * nd;
    // last chunk: 8 floats at node*64 + slane*8
    const float4* lp = (const float4*)(g_last + node * C_DIM + slane * 8);
    float4 l0 = lp[0];
    float4 l1 = lp[1];

    float y0 = fminf(fmaxf(fmaf(s, a[0].x, l0.x), 0.0f), 1.0f);
    float y1 = fminf(fmaxf(fmaf(s, a[0].y, l0.y), 0.0f), 1.0f);
    float y2 = fminf(fmaxf(fmaf(s, a[1].x, l0.z), 0.0f), 1.0f);
    float y3 = fminf(fmaxf(fmaf(s, a[1].y, l0.w), 0.0f), 1.0f);
    float y4 = fminf(fmaxf(fmaf(s, a[2].x, l1.x), 0.0f), 1.0f);
    float y5 = fminf(fmaxf(fmaf(s, a[2].y, l1.y), 0.0f), 1.0f);
    float y6 = fminf(fmaxf(fmaf(s, a[3].x, l1.z), 0.0f), 1.0f);
    float y7 = fminf(fmaxf(fmaf(s, a[3].y, l1.w), 0.0f), 1.0f);

    if (yout) {
        float4* op = (float4*)(yout + node * C_DIM + slane * 8);
        op[0] = make_float4(y0, y1, y2, y3);
        op[1] = make_float4(y4, y5, y6, y7);
    } else {
        uint4 o;
        *(__half2*)&o.x = __floats2half2_rn(nd * y0, nd * y1);
        *(__half2*)&o.y = __floats2half2_rn(nd * y2, nd * y3);
        *(__half2*)&o.z = __floats2half2_rn(nd * y4, nd * y5);
        *(__half2*)&o.w = __floats2half2_rn(nd * y6, nd * y7);
        zout[node * 8 + slane] = o;
    }
}

// ------------------------------------------------------------------
extern "C" void kernel_launch(void* const* d_in, const int* in_sizes, int n_in,
                              void* d_out, int out_size) {
    const float* labels   = (const float*)d_in[0];
    const void*  mask_raw = d_in[1];
    const int*   src      = (const int*)d_in[2];
    const int*   dst      = (const int*)d_in[3];
    float*       out      = (float*)d_out;

    const int N = N_NODES;
    const int E = E_EDGES;

    detect_mask_kernel<<<1, 256>>>((const unsigned char*)mask_raw);

    // CSR build
    zero_deg_kernel<<<(N + 255) / 256, 256>>>(N);
    count_deg_kernel<<<(E + 255) / 256, 256>>>(dst, E);
    scan_pass1_kernel<<<NBLK_SCAN, SCAN_TILE>>>(N);
    scan_pass2_kernel<<<1, 128>>>(N);
    scan_pass3_kernel<<<NBLK_SCAN, SCAN_TILE>>>(N);
    fill_csr_kernel<<<(E + 255) / 256, 256>>>(src, dst, E);

    // init
    init_kernel<<<(N * C2 + 255) / 256, 256>>>(labels, mask_raw, N);

    // 10 propagation layers (8 threads per node => N*8 threads)
    const int prop_threads = N * 8;
    const int prop_blocks  = (prop_threads + 255) / 256;
    for (int layer = 0; layer < NUM_LAYERS; layer++) {
        int flip = layer & 1;
        float* yo = (layer == NUM_LAYERS - 1) ? out : nullptr;
        prop_kernel<<<prop_blocks, 256>>>(flip, yo);
    }
}